// round 16
// baseline (speedup 1.0000x reference)
#include <cuda_runtime.h>

// FoRefLoss: sum over B rows of (dx^2 + dy^2 + wrapped_angle^2), B=8388608.
// 256-bit-load probe of the champion: same grid (1024x256), same dynamic
// mod-3 angle-mask walk, same fused deterministic finalize — but the stream
// is consumed as float8s via ld.global.v8.f32 (sm_100+ LDG.E.256): half the
// LDG issue count and 256B request granules. n8 = 3145728 = 262144 threads
// x 12 iterations exactly. Float base 8k advances by 8*stride ≡ 2 (mod 3)
// per iteration; component c of a float8 is the angle iff (m + c) % 3 == 2.
// Angle term in turn-space: t = 2*min(frac(|d|), 1-frac(|d|)), term t^2.

#define NBLOCKS 1024
#define NTHREADS 256

__device__ float g_partials[NBLOCKS];
__device__ unsigned int g_arrived = 0;

__device__ __forceinline__ float vcomp(float p, float l, bool is_angle) {
    float d = p - l;              // difference in "turns" (full circle = 1.0)
    float ad = fabsf(d);
    float f = ad - floorf(ad);    // frac in [0,1)
    float w = fminf(f, 1.0f - f); // folded to [0, 0.5]
    return is_angle ? (w + w) : d; // angle: 2w = clamped_angle/pi; else diff
}

__device__ __forceinline__ void ldg256(const float* p, float r[8]) {
    asm volatile("ld.global.v8.f32 {%0,%1,%2,%3,%4,%5,%6,%7}, [%8];"
                 : "=f"(r[0]), "=f"(r[1]), "=f"(r[2]), "=f"(r[3]),
                   "=f"(r[4]), "=f"(r[5]), "=f"(r[6]), "=f"(r[7])
                 : "l"(p));
}

__global__ void __launch_bounds__(NTHREADS)
foref_loss_kernel(const float* __restrict__ pred,
                  const float* __restrict__ lab,
                  int n_floats,           // 25165824
                  float* __restrict__ out)
{
    const int stride = NBLOCKS * NTHREADS;      // 262144 threads
    int tid0 = blockIdx.x * NTHREADS + threadIdx.x;

    float sum = 0.0f;
    int n8 = n_floats / 8;        // 3145728
    int iters = n8 / stride;      // 12 exactly

    // float base index of this thread's float8 = 8*k; m = (8*k) % 3.
    int k = tid0;
    int m = (2 * tid0) % 3;       // 8 ≡ 2 (mod 3)

    #pragma unroll 2
    for (int it = 0; it < iters; ++it) {
        float p[8], l[8];
        ldg256(pred + 8 * (size_t)k, p);
        ldg256(lab  + 8 * (size_t)k, l);
        // component c is the angle iff (m + c) % 3 == 2
        #pragma unroll
        for (int c = 0; c < 8; ++c) {
            bool ang = (((m + c) % 3) == 2);
            float v = vcomp(p[c], l[c], ang);
            sum = fmaf(v, v, sum);
        }
        k += stride;
        m = (m == 0) ? 2 : (m - 1);   // 8*stride ≡ 2 (mod 3) -> m += 2 ≡ m-1
    }

    // generic scalar tail for leftover floats (empty for n_floats = 25165824)
    for (int i = n8 * 8 + tid0; i < n_floats; i += stride) {
        bool ang = ((i % 3) == 2);
        float v = vcomp(pred[i], lab[i], ang);
        sum = fmaf(v, v, sum);
    }

    // intra-block reduce
    #pragma unroll
    for (int off = 16; off > 0; off >>= 1)
        sum += __shfl_down_sync(0xFFFFFFFFu, sum, off);

    __shared__ float smem[NTHREADS / 32];
    __shared__ bool is_last;
    int lane = threadIdx.x & 31;
    int wid  = threadIdx.x >> 5;
    if (lane == 0) smem[wid] = sum;
    __syncthreads();

    if (wid == 0) {
        float v = (lane < NTHREADS / 32) ? smem[lane] : 0.0f;
        #pragma unroll
        for (int off = 4; off > 0; off >>= 1)
            v += __shfl_down_sync(0xFFFFFFFFu, v, off);
        if (lane == 0) {
            g_partials[blockIdx.x] = v;
            __threadfence();
            unsigned int t = atomicAdd(&g_arrived, 1u);
            is_last = (t == (unsigned int)(gridDim.x - 1));
        }
    }
    __syncthreads();

    if (is_last) {
        // all partials are globally visible now; reduce in fixed order
        float v = 0.0f;
        for (int i = threadIdx.x; i < NBLOCKS; i += NTHREADS)
            v += g_partials[i];

        #pragma unroll
        for (int off = 16; off > 0; off >>= 1)
            v += __shfl_down_sync(0xFFFFFFFFu, v, off);

        if (lane == 0) smem[wid] = v;
        __syncthreads();

        if (wid == 0) {
            float t2 = (lane < NTHREADS / 32) ? smem[lane] : 0.0f;
            #pragma unroll
            for (int off = 4; off > 0; off >>= 1)
                t2 += __shfl_down_sync(0xFFFFFFFFu, t2, off);
            if (lane == 0) {
                out[0] = t2;
                g_arrived = 0;  // reset for next graph replay
            }
        }
    }
}

extern "C" void kernel_launch(void* const* d_in, const int* in_sizes, int n_in,
                              void* d_out, int out_size)
{
    const float* pred = (const float*)d_in[0];
    const float* lab  = (const float*)d_in[1];
    float* out = (float*)d_out;

    int n_floats = in_sizes[0];   // 25165824

    foref_loss_kernel<<<NBLOCKS, NTHREADS>>>(pred, lab, n_floats, out);
}

// round 17
// speedup vs baseline: 1.1655x; 1.1655x over previous
#include <cuda_runtime.h>

// FoRefLoss: sum over B rows of (dx^2 + dy^2 + wrapped_angle^2), B=8388608.
// FINAL (16-round matrix closed; 256-bit-load probe R16 regressed to 40.8us
// confirming 128-bit lane-interleaved loads are the memory-system optimum):
// coalesced float4 grid-stride, 1024 CTAs x 256 threads — the most-reproduced
// best configuration (totals 35.30-36.19us across 6 benches). HBM-read-bound
// at the empirical ~6.0-6.2 TB/s ceiling (74-78% of 8 TB/s spec); traffic is
// compulsory (201 MB read once, 4 B out). Compute pipes <=13%.
//   - angle term in turn-space: t = 2*min(frac(|d|), 1-frac(|d|)), term t^2
//     (identical to clamp(|d*2pi| mod 2pi)/pi; no fmod, no pi constants)
//   - single kernel: last-arriving block reduces the 1024 partials in fixed
//     order (deterministic across replays) and resets the arrival counter.

#define NBLOCKS 1024
#define NTHREADS 256

__device__ float g_partials[NBLOCKS];
__device__ unsigned int g_arrived = 0;

__device__ __forceinline__ float vcomp(float p, float l, bool is_angle) {
    float d = p - l;              // difference in "turns" (full circle = 1.0)
    float ad = fabsf(d);
    float f = ad - floorf(ad);    // frac in [0,1)
    float w = fminf(f, 1.0f - f); // folded to [0, 0.5]
    return is_angle ? (w + w) : d; // angle: 2w = clamped_angle/pi; else diff
}

__global__ void __launch_bounds__(NTHREADS)
foref_loss_kernel(const float4* __restrict__ pred,
                  const float4* __restrict__ lab,
                  int n4,                 // total float4 count per tensor
                  float* __restrict__ out)
{
    const int stride = NBLOCKS * NTHREADS;      // 262144; 262144 % 3 == 1
    int tid0 = blockIdx.x * NTHREADS + threadIdx.x;

    float sum = 0.0f;
    int iters = n4 / stride;   // 24 exactly for n4 = 6291456

    int k = tid0;
    int m = k % 3;

    #pragma unroll 2
    for (int it = 0; it < iters; ++it) {
        float4 p = pred[k];
        float4 l = lab[k];
        // component c is angle iff (k + c) % 3 == 2
        bool aA = (m == 2);   // c = 0 and c = 3
        bool aB = (m == 1);   // c = 1
        bool aC = (m == 0);   // c = 2
        float v;
        v = vcomp(p.x, l.x, aA); sum = fmaf(v, v, sum);
        v = vcomp(p.y, l.y, aB); sum = fmaf(v, v, sum);
        v = vcomp(p.z, l.z, aC); sum = fmaf(v, v, sum);
        v = vcomp(p.w, l.w, aA); sum = fmaf(v, v, sum);
        k += stride;
        m = (m == 2) ? 0 : (m + 1);   // stride % 3 == 1
    }
    // generic tail (empty for n4 = 6291456)
    if (k < n4) {
        float4 p = pred[k];
        float4 l = lab[k];
        bool aA = (m == 2), aB = (m == 1), aC = (m == 0);
        float v;
        v = vcomp(p.x, l.x, aA); sum = fmaf(v, v, sum);
        v = vcomp(p.y, l.y, aB); sum = fmaf(v, v, sum);
        v = vcomp(p.z, l.z, aC); sum = fmaf(v, v, sum);
        v = vcomp(p.w, l.w, aA); sum = fmaf(v, v, sum);
    }

    // intra-block reduce
    #pragma unroll
    for (int off = 16; off > 0; off >>= 1)
        sum += __shfl_down_sync(0xFFFFFFFFu, sum, off);

    __shared__ float smem[NTHREADS / 32];
    __shared__ bool is_last;
    int lane = threadIdx.x & 31;
    int wid  = threadIdx.x >> 5;
    if (lane == 0) smem[wid] = sum;
    __syncthreads();

    if (wid == 0) {
        float v = (lane < NTHREADS / 32) ? smem[lane] : 0.0f;
        #pragma unroll
        for (int off = 4; off > 0; off >>= 1)
            v += __shfl_down_sync(0xFFFFFFFFu, v, off);
        if (lane == 0) {
            g_partials[blockIdx.x] = v;
            __threadfence();
            unsigned int t = atomicAdd(&g_arrived, 1u);
            is_last = (t == (unsigned int)(gridDim.x - 1));
        }
    }
    __syncthreads();

    if (is_last) {
        // all partials are globally visible now; reduce in fixed order
        float v = 0.0f;
        for (int i = threadIdx.x; i < NBLOCKS; i += NTHREADS)
            v += g_partials[i];

        #pragma unroll
        for (int off = 16; off > 0; off >>= 1)
            v += __shfl_down_sync(0xFFFFFFFFu, v, off);

        if (lane == 0) smem[wid] = v;
        __syncthreads();

        if (wid == 0) {
            float t2 = (lane < NTHREADS / 32) ? smem[lane] : 0.0f;
            #pragma unroll
            for (int off = 4; off > 0; off >>= 1)
                t2 += __shfl_down_sync(0xFFFFFFFFu, t2, off);
            if (lane == 0) {
                out[0] = t2;
                g_arrived = 0;  // reset for next graph replay
            }
        }
    }
}

extern "C" void kernel_launch(void* const* d_in, const int* in_sizes, int n_in,
                              void* d_out, int out_size)
{
    const float4* pred = (const float4*)d_in[0];
    const float4* lab  = (const float4*)d_in[1];
    float* out = (float*)d_out;

    int n_floats = in_sizes[0];   // 25165824
    int n4 = n_floats / 4;        // 6291456

    foref_loss_kernel<<<NBLOCKS, NTHREADS>>>(pred, lab, n4, out);
}